// round 2
// baseline (speedup 1.0000x reference)
#include <cuda_runtime.h>

#define Bc 8
#define Hc 320
#define Wc 1024
#define NPIX (Bc*Hc*Wc)      // 2621440 per channel
#define TLX 32
#define TLY 16
#define CAP 768

// Scratch (static device globals — no allocation)
__device__ unsigned g_mask[NPIX/32];   // found bitmask, 1 bit per pixel
__device__ float2   g_v[NPIX];         // (vx, vy) per pixel

// ---------------------------------------------------------------------------
// Kernel 1: sparsity filter + windowed nearest-correspondence match.
// Writes output channels 2..5, found bitmask, and per-pixel (vx,vy).
// ---------------------------------------------------------------------------
__global__ void __launch_bounds__(256) match_kernel(
    const float* __restrict__ src,
    const float* __restrict__ dst,
    const float* __restrict__ xx,
    const float* __restrict__ yy,
    float* __restrict__ out)
{
    __shared__ int2 s_off[105];
    int tid = threadIdx.x;
    if (tid < 105) s_off[tid] = make_int2((int)xx[tid], (int)yy[tid]);
    __syncthreads();

    int gid = blockIdx.x * 256 + tid;          // grid exactly covers NPIX
    int x  = gid & (Wc - 1);
    int yb = gid >> 10;                        // b*H + y
    int y  = yb % Hc;
    int b  = yb / Hc;
    int rowbase = yb * Wc;                     // (b*H + y) * W

    bool active = src[gid] > 0.5f;
    bool kept = false;
    if (active) {
        // "preceding" offsets in the 5x5 sparsity window:
        //   dy in {-2,-1}, dx in [-2,2]   and   dy == 0, dx in {-2,-1}
        bool hit = false;
        #pragma unroll
        for (int dy = -2; dy <= 0; dy++) {
            int y2 = y + dy;
            if ((unsigned)y2 >= (unsigned)Hc) continue;
            int dxmax = (dy == 0) ? -1 : 2;
            #pragma unroll
            for (int dx = -2; dx <= 2; dx++) {
                if (dx > dxmax) break;
                int x2 = x + dx;
                if ((unsigned)x2 < (unsigned)Wc) {
                    if (src[(b*Hc + y2)*Wc + x2] > 0.5f) hit = true;
                }
            }
        }
        kept = !hit;
    }

    bool found = false;
    float vx = 0.f, vy = 0.f;
    if (kept) {
        for (int i = 0; i < 105; i++) {
            int dx = s_off[i].x, dy = s_off[i].y;
            int x2 = x + dx, y2 = y + dy;
            if ((unsigned)x2 < (unsigned)Wc && (unsigned)y2 < (unsigned)Hc) {
                if (dst[(b*Hc + y2)*Wc + x2] > 0.5f) {
                    found = true; vx = (float)dx; vy = (float)dy;
                    break;
                }
            }
        }
    }

    unsigned m = __ballot_sync(0xFFFFFFFFu, found);
    if ((tid & 31) == 0) g_mask[gid >> 5] = m;
    g_v[gid] = make_float2(vx, vy);

    float fx = (float)x, fy = (float)y;
    float mf = found ? 1.f : 0.f;
    out[2*NPIX + gid] = fx * mf;               // orgpts_x
    out[3*NPIX + gid] = fy * mf;               // orgpts_y
    out[4*NPIX + gid] = (fx + vx) * mf;        // correspts_x
    out[5*NPIX + gid] = (fy + vy) * mf;        // correspts_y
    (void)rowbase;
}

// ---------------------------------------------------------------------------
// Kernel 2: sparse splat-as-gather of the 41x41 distance-weighted kernel.
// One block per 32x16 output tile; compact halo points into shared, then each
// thread register-accumulates (den, sum_wx, sum_wy) for 2 pixels.
// ---------------------------------------------------------------------------
__global__ void __launch_bounds__(256) splat_kernel(float* __restrict__ out)
{
    __shared__ float  s_K[41*41];
    __shared__ float4 s_pts[CAP];
    __shared__ int    s_n;

    int tx = threadIdx.x;      // 0..31
    int ty = threadIdx.y;      // 0..7
    int tid = ty * 32 + tx;
    if (tid == 0) s_n = 0;

    // Build weight table: K[dy+20][dx+20] = 0.7*exp(-sqrt(dx^2+dy^2)*1.9/24)
    for (int i = tid; i < 41*41; i += 256) {
        int dyk = i / 41 - 20, dxk = i % 41 - 20;
        s_K[i] = 0.7f * expf(-sqrtf((float)(dxk*dxk + dyk*dyk)) * (1.9f/24.f));
    }

    int x0 = blockIdx.x * TLX;
    int y0 = blockIdx.y * TLY;
    int b  = blockIdx.z;
    __syncthreads();

    // Gather halo points: rows [y0-20, y0+35], x in [x0-20, x0+51]
    int wx = x0 >> 5;
    for (int t = tid; t < 56*3; t += 256) {
        int r  = t / 3;
        int wi = t % 3 - 1;
        int ry = y0 - 20 + r;
        int wj = wx + wi;
        if ((unsigned)ry < (unsigned)Hc && (unsigned)wj < 32u) {
            unsigned word = g_mask[(b*Hc + ry)*32 + wj];
            if (wi == -1) word &= 0xFFFFF000u;   // keep x >= x0-20
            if (wi == +1) word &= 0x000FFFFFu;   // keep x <= x0+51
            while (word) {
                int j = __ffs(word) - 1;
                word &= word - 1;
                int px = (wj << 5) + j;
                float2 v = g_v[(b*Hc + ry)*Wc + px];
                int slot = atomicAdd(&s_n, 1);
                if (slot < CAP)
                    s_pts[slot] = make_float4(__int_as_float(px - x0 + 20),
                                              __int_as_float(r),
                                              v.x, v.y);
            }
        }
    }
    __syncthreads();

    int n = min(s_n, CAP);
    float den0=0.f, sx0=0.f, sy0=0.f;
    float den1=0.f, sx1=0.f, sy1=0.f;

    for (int i = 0; i < n; i++) {
        float4 p = s_pts[i];
        int u = __float_as_int(p.x) - tx;        // dx+20 for this thread's column
        if ((unsigned)u <= 40u) {
            int v0 = __float_as_int(p.y) - ty;   // dy+20 for pixel row y0+ty
            if ((unsigned)v0 <= 40u) {
                float w = s_K[v0*41 + u];
                den0 += w; sx0 = fmaf(w, p.z, sx0); sy0 = fmaf(w, p.w, sy0);
            }
            int v1 = v0 - 8;                     // pixel row y0+ty+8
            if ((unsigned)v1 <= 40u) {
                float w = s_K[v1*41 + u];
                den1 += w; sx1 = fmaf(w, p.z, sx1); sy1 = fmaf(w, p.w, sy1);
            }
        }
    }

    int x   = x0 + tx;
    int y   = y0 + ty;
    int idx = (b*Hc + y)*Wc + x;
    float fx = (float)x;

    float r0 = 1.f / (den0 + 1.6f);
    out[idx]         = fx + sx0 * r0;            // morphedx
    out[NPIX + idx]  = (float)y + sy0 * r0;      // morphedy

    int idx1 = idx + 8*Wc;
    float r1 = 1.f / (den1 + 1.6f);
    out[idx1]        = fx + sx1 * r1;
    out[NPIX + idx1] = (float)(y + 8) + sy1 * r1;
}

extern "C" void kernel_launch(void* const* d_in, const int* in_sizes, int n_in,
                              void* d_out, int out_size)
{
    const float* src = (const float*)d_in[0];  // binMapsrc
    const float* dst = (const float*)d_in[1];  // binMapdst
    const float* xx  = (const float*)d_in[2];
    const float* yy  = (const float*)d_in[3];
    float* out = (float*)d_out;

    match_kernel<<<NPIX/256, 256>>>(src, dst, xx, yy, out);

    dim3 grid(Wc/TLX, Hc/TLY, Bc);   // 32 x 20 x 8 = 5120 blocks
    dim3 blk(32, 8);
    splat_kernel<<<grid, blk>>>(out);

    (void)in_sizes; (void)n_in; (void)out_size;
}

// round 4
// speedup vs baseline: 1.4227x; 1.4227x over previous
#include <cuda_runtime.h>

#define Bc 8
#define Hc 320
#define Wc 1024
#define WW 32                    // 32-bit words per row
#define NPIX (Bc*Hc*Wc)          // 2621440
#define NWORD (NPIX/32)
#define TLX 32
#define TLY 32
#define CAP 768

// Static device scratch (no allocations)
__device__ unsigned g_srcm[NWORD];
__device__ unsigned g_dstm[NWORD];
__device__ unsigned g_mask[NWORD];   // found bitmask
__device__ float2   g_v[NPIX];       // (vx,vy), written sparsely at found px
__device__ float    g_K[41*41];      // splat weight table
__device__ int      g_rank[7*15];    // argsort-order rank of each (dy,dx) offset

// ---------------------------------------------------------------------------
// Kernel 0a: src/dst bitmasks (bandwidth-bound, ~21MB read)
// ---------------------------------------------------------------------------
__global__ void __launch_bounds__(256) bitmask_kernel(
    const float* __restrict__ src, const float* __restrict__ dst)
{
    int gid = blockIdx.x * 256 + threadIdx.x;
    unsigned bs = __ballot_sync(0xFFFFFFFFu, src[gid] > 0.5f);
    unsigned bd = __ballot_sync(0xFFFFFFFFu, dst[gid] > 0.5f);
    if ((threadIdx.x & 31) == 0) { g_srcm[gid >> 5] = bs; g_dstm[gid >> 5] = bd; }
}

// ---------------------------------------------------------------------------
// Kernel 0b: precompute 41x41 weight table + offset rank LUT.
// rank reproduces the EXACT np.argsort order (including unstable tie order)
// because it is read straight from the xx/yy inputs.
// ---------------------------------------------------------------------------
__global__ void ktab_kernel(const float* __restrict__ xx,
                            const float* __restrict__ yy)
{
    int i = blockIdx.x * 256 + threadIdx.x;
    if (i < 41*41) {
        int dy = i / 41 - 20, dx = i % 41 - 20;
        g_K[i] = 0.7f * expf(-sqrtf((float)(dx*dx + dy*dy)) * (1.9f/24.f));
    }
    if (i < 105) {
        int dx = (int)xx[i], dy = (int)yy[i];
        g_rank[(dy + 3)*15 + (dx + 7)] = i;
    }
}

// ---------------------------------------------------------------------------
// 15/5-bit neighborhood window extraction from 3 mask words.
// Returned bit k corresponds to dx = k - radius for this lane's pixel.
// ---------------------------------------------------------------------------
__device__ __forceinline__ unsigned win_extract(
    unsigned l, unsigned m, unsigned r, int j, int radius)
{
    if (j < 16) {
        unsigned long long lm = ((unsigned long long)m << 32) | l;
        return (unsigned)(lm >> (32 + j - radius));
    } else {
        unsigned long long mr = ((unsigned long long)r << 32) | m;
        return (unsigned)(mr >> (j - radius));
    }
}

// ---------------------------------------------------------------------------
// Kernel 1: sparsity filter + nearest-correspondence via bitmask windows.
// Writes output channels 2..5, found bitmask, sparse (vx,vy).
// ---------------------------------------------------------------------------
__global__ void __launch_bounds__(256) match_kernel(float* __restrict__ out)
{
    __shared__ int s_rank[7*15];
    if (threadIdx.x < 105) s_rank[threadIdx.x] = g_rank[threadIdx.x];
    __syncthreads();

    int gid = blockIdx.x * 256 + threadIdx.x;
    int j   = gid & 31;            // lane == bit index (warp-aligned words)
    int wi  = gid >> 5;            // global word index
    int wx  = wi & (WW - 1);
    int yb  = wi >> 5;             // b*H + y
    int y   = yb % Hc;
    int b   = yb / Hc;

    // --- sparsity check: src rows y-2..y, words wx-1..wx+1 (broadcast LDGs)
    unsigned sw[3][3];
    #pragma unroll
    for (int r = 0; r < 3; r++) {
        int ry = y - 2 + r;
        #pragma unroll
        for (int c = 0; c < 3; c++) {
            int rc = wx - 1 + c;
            unsigned v = 0;
            if ((unsigned)ry < (unsigned)Hc && (unsigned)rc < (unsigned)WW)
                v = g_srcm[(b*Hc + ry)*WW + rc];
            sw[r][c] = v;
        }
    }
    bool active = (sw[2][1] >> j) & 1u;
    // preceding neighbors: dy=-2,-1 full dx in [-2,2]; dy=0 dx in {-2,-1}
    unsigned h0 = win_extract(sw[0][0], sw[0][1], sw[0][2], j, 2) & 31u;
    unsigned h1 = win_extract(sw[1][0], sw[1][1], sw[1][2], j, 2) & 31u;
    unsigned h2 = win_extract(sw[2][0], sw[2][1], sw[2][2], j, 2) & 3u;
    bool kept = active && !(h0 | h1 | h2);

    bool found = false;
    float vx = 0.f, vy = 0.f;
    if (__ballot_sync(0xFFFFFFFFu, kept)) {
        int bestkey = 1 << 30, bdx = 0, bdy = 0;
        #pragma unroll
        for (int r = 0; r < 7; r++) {
            int dy = r - 3;
            int ry = y + dy;
            unsigned l = 0, m = 0, rr = 0;
            if ((unsigned)ry < (unsigned)Hc) {
                int base = (b*Hc + ry)*WW;
                if (wx > 0)      l  = g_dstm[base + wx - 1];
                m = g_dstm[base + wx];
                if (wx < WW - 1) rr = g_dstm[base + wx + 1];
            }
            if (kept) {
                unsigned win = win_extract(l, m, rr, j, 7) & 0x7FFFu;
                while (win) {
                    int k = __ffs(win) - 1; win &= win - 1;
                    // key = exact position in the argsort-ordered offset list
                    int key = s_rank[r*15 + k];
                    if (key < bestkey) { bestkey = key; bdx = k - 7; bdy = dy; }
                }
            }
        }
        if (kept && bestkey < (1 << 30)) {
            found = true; vx = (float)bdx; vy = (float)bdy;
        }
    }

    unsigned fb = __ballot_sync(0xFFFFFFFFu, found);
    if (j == 0) g_mask[wi] = fb;
    if (found)  g_v[gid] = make_float2(vx, vy);   // sparse write

    int x = gid & (Wc - 1);
    float fx = (float)x, fy = (float)y;
    float mf = found ? 1.f : 0.f;
    out[2*NPIX + gid] = fx * mf;               // orgpts_x
    out[3*NPIX + gid] = fy * mf;               // orgpts_y
    out[4*NPIX + gid] = (fx + vx) * mf;        // correspts_x
    out[5*NPIX + gid] = (fy + vy) * mf;        // correspts_y
}

// ---------------------------------------------------------------------------
// Kernel 2: sparse splat-as-gather, 32x32 tile, 4 rows per thread.
// Scan-based compaction (1 atomic per warp instead of per point).
// ---------------------------------------------------------------------------
__global__ void __launch_bounds__(256) splat_kernel(float* __restrict__ out)
{
    __shared__ float  s_K[41*41];
    __shared__ float4 s_pts[CAP];
    __shared__ int    s_base[8];
    __shared__ int    s_n;

    int tid  = threadIdx.x;
    int lane = tid & 31;
    int wrp  = tid >> 5;
    int tx   = lane;
    int ty   = wrp;                 // 0..7; rows ty, ty+8, ty+16, ty+24
    if (tid == 0) s_n = 0;
    for (int i = tid; i < 41*41; i += 256) s_K[i] = g_K[i];

    int x0 = blockIdx.x * TLX;
    int y0 = blockIdx.y * TLY;
    int b  = blockIdx.z;
    __syncthreads();

    // --- gather halo points: rows [y0-20, y0+51] x words wx-1..wx+1 (216 words)
    unsigned word = 0; int ry = 0, wj = 0;
    if (tid < 216) {
        int r   = tid / 3;
        int wi2 = tid % 3 - 1;
        ry = y0 - 20 + r;
        wj = (x0 >> 5) + wi2;
        if ((unsigned)ry < (unsigned)Hc && (unsigned)wj < (unsigned)WW) {
            word = g_mask[(b*Hc + ry)*WW + wj];
            if (wi2 == -1) word &= 0xFFFFF000u;   // keep x >= x0-20
            if (wi2 ==  1) word &= 0x000FFFFFu;   // keep x <= x0+51
        }
    }
    int cnt  = __popc(word);
    int incl = cnt;
    #pragma unroll
    for (int d = 1; d < 32; d <<= 1) {
        int n2 = __shfl_up_sync(0xFFFFFFFFu, incl, d);
        if (lane >= d) incl += n2;
    }
    int excl = incl - cnt;
    if (lane == 31) s_base[wrp] = atomicAdd(&s_n, incl);
    __syncthreads();
    {
        int base = s_base[wrp] + excl;
        unsigned w2 = word; int k = 0;
        while (w2) {
            int jb = __ffs(w2) - 1; w2 &= w2 - 1;
            int px = (wj << 5) + jb;
            float2 v = g_v[(b*Hc + ry)*Wc + px];
            int slot = base + k; k++;
            if (slot < CAP)
                s_pts[slot] = make_float4(__int_as_float(px - x0 + 20),
                                          __int_as_float(ry - (y0 - 20)),
                                          v.x, v.y);
        }
    }
    __syncthreads();

    int n = min(s_n, CAP);
    float den[4] = {0,0,0,0}, sx[4] = {0,0,0,0}, sy[4] = {0,0,0,0};

    for (int i = 0; i < n; i++) {
        float4 p = s_pts[i];
        int u = __float_as_int(p.x) - tx;           // dx+20
        if ((unsigned)u <= 40u) {
            int v0 = __float_as_int(p.y) - ty;      // dy+20 for row y0+ty
            #pragma unroll
            for (int kk = 0; kk < 4; kk++) {
                int v = v0 - 8*kk;
                if ((unsigned)v <= 40u) {
                    float w = s_K[v*41 + u];
                    den[kk] += w;
                    sx[kk] = fmaf(w, p.z, sx[kk]);
                    sy[kk] = fmaf(w, p.w, sy[kk]);
                }
            }
        }
    }

    int x = x0 + tx;
    float fx = (float)x;
    #pragma unroll
    for (int kk = 0; kk < 4; kk++) {
        int y   = y0 + ty + 8*kk;
        int idx = (b*Hc + y)*Wc + x;
        float rcp = 1.f / (den[kk] + 1.6f);
        out[idx]        = fx + sx[kk] * rcp;        // morphedx
        out[NPIX + idx] = (float)y + sy[kk] * rcp;  // morphedy
    }
}

extern "C" void kernel_launch(void* const* d_in, const int* in_sizes, int n_in,
                              void* d_out, int out_size)
{
    const float* src = (const float*)d_in[0];  // binMapsrc
    const float* dst = (const float*)d_in[1];  // binMapdst
    const float* xx  = (const float*)d_in[2];
    const float* yy  = (const float*)d_in[3];
    float* out = (float*)d_out;

    bitmask_kernel<<<NPIX/256, 256>>>(src, dst);
    ktab_kernel<<<7, 256>>>(xx, yy);
    match_kernel<<<NPIX/256, 256>>>(out);

    dim3 grid(Wc/TLX, Hc/TLY, Bc);   // 32 x 10 x 8 = 2560 blocks
    splat_kernel<<<grid, 256>>>(out);

    (void)in_sizes; (void)n_in; (void)out_size;
}

// round 5
// speedup vs baseline: 1.6830x; 1.1830x over previous
#include <cuda_runtime.h>

#define Bc 8
#define Hc 320
#define Wc 1024
#define WW 32                    // 32-bit words per row
#define NPIX (Bc*Hc*Wc)          // 2621440
#define NWORD (NPIX/32)
#define TLX 32
#define TLY 32
#define CAP 1024
#define HROWS 72                 // halo rows per tile: [y0-20, y0+51]

// Static device scratch (no allocations)
__device__ unsigned g_srcm[NWORD];
__device__ unsigned g_dstm[NWORD];
__device__ unsigned g_mask[NWORD];   // found bitmask
__device__ float2   g_v[NPIX];       // (vx,vy), written sparsely at found px
__device__ float    g_K[41*41];      // splat weight table
__device__ int      g_rank[7*15];    // argsort-order rank of each (dy,dx) offset

// ---------------------------------------------------------------------------
// Kernel 0: src/dst bitmasks (BW-bound) + fused K-table / rank-LUT build.
// ---------------------------------------------------------------------------
__global__ void __launch_bounds__(256) bitmask_kernel(
    const float* __restrict__ src, const float* __restrict__ dst,
    const float* __restrict__ xx,  const float* __restrict__ yy)
{
    int gid = blockIdx.x * 256 + threadIdx.x;
    unsigned bs = __ballot_sync(0xFFFFFFFFu, src[gid] > 0.5f);
    unsigned bd = __ballot_sync(0xFFFFFFFFu, dst[gid] > 0.5f);
    if ((threadIdx.x & 31) == 0) { g_srcm[gid >> 5] = bs; g_dstm[gid >> 5] = bd; }

    if (blockIdx.x < 7) {                      // fused one-shot LUT build
        int i = blockIdx.x * 256 + threadIdx.x;
        if (i < 41*41) {
            int dy = i / 41 - 20, dx = i % 41 - 20;
            g_K[i] = 0.7f * expf(-sqrtf((float)(dx*dx + dy*dy)) * (1.9f/24.f));
        }
        if (i < 105) {
            int dx = (int)xx[i], dy = (int)yy[i];
            g_rank[(dy + 3)*15 + (dx + 7)] = i;   // exact argsort order
        }
    }
}

// ---------------------------------------------------------------------------
// 15/5-bit neighborhood window extraction from 3 mask words.
// ---------------------------------------------------------------------------
__device__ __forceinline__ unsigned win_extract(
    unsigned l, unsigned m, unsigned r, int j, int radius)
{
    if (j < 16) {
        unsigned long long lm = ((unsigned long long)m << 32) | l;
        return (unsigned)(lm >> (32 + j - radius));
    } else {
        unsigned long long mr = ((unsigned long long)r << 32) | m;
        return (unsigned)(mr >> (j - radius));
    }
}

// ---------------------------------------------------------------------------
// Kernel 1: sparsity filter + nearest-correspondence via bitmask windows.
// ---------------------------------------------------------------------------
__global__ void __launch_bounds__(256) match_kernel(float* __restrict__ out)
{
    __shared__ int s_rank[7*15];
    if (threadIdx.x < 105) s_rank[threadIdx.x] = g_rank[threadIdx.x];
    __syncthreads();

    int gid = blockIdx.x * 256 + threadIdx.x;
    int j   = gid & 31;
    int wi  = gid >> 5;
    int wx  = wi & (WW - 1);
    int yb  = wi >> 5;             // b*H + y
    int y   = yb % Hc;
    int b   = yb / Hc;

    unsigned sw[3][3];
    #pragma unroll
    for (int r = 0; r < 3; r++) {
        int ry = y - 2 + r;
        #pragma unroll
        for (int c = 0; c < 3; c++) {
            int rc = wx - 1 + c;
            unsigned v = 0;
            if ((unsigned)ry < (unsigned)Hc && (unsigned)rc < (unsigned)WW)
                v = g_srcm[(b*Hc + ry)*WW + rc];
            sw[r][c] = v;
        }
    }
    bool active = (sw[2][1] >> j) & 1u;
    unsigned h0 = win_extract(sw[0][0], sw[0][1], sw[0][2], j, 2) & 31u;
    unsigned h1 = win_extract(sw[1][0], sw[1][1], sw[1][2], j, 2) & 31u;
    unsigned h2 = win_extract(sw[2][0], sw[2][1], sw[2][2], j, 2) & 3u;
    bool kept = active && !(h0 | h1 | h2);

    bool found = false;
    float vx = 0.f, vy = 0.f;
    if (__ballot_sync(0xFFFFFFFFu, kept)) {
        int bestkey = 1 << 30, bdx = 0, bdy = 0;
        #pragma unroll
        for (int r = 0; r < 7; r++) {
            int dy = r - 3;
            int ry = y + dy;
            unsigned l = 0, m = 0, rr = 0;
            if ((unsigned)ry < (unsigned)Hc) {
                int base = (b*Hc + ry)*WW;
                if (wx > 0)      l  = g_dstm[base + wx - 1];
                m = g_dstm[base + wx];
                if (wx < WW - 1) rr = g_dstm[base + wx + 1];
            }
            if (kept) {
                unsigned win = win_extract(l, m, rr, j, 7) & 0x7FFFu;
                while (win) {
                    int k = __ffs(win) - 1; win &= win - 1;
                    int key = s_rank[r*15 + k];
                    if (key < bestkey) { bestkey = key; bdx = k - 7; bdy = dy; }
                }
            }
        }
        if (kept && bestkey < (1 << 30)) {
            found = true; vx = (float)bdx; vy = (float)bdy;
        }
    }

    unsigned fb = __ballot_sync(0xFFFFFFFFu, found);
    if (j == 0) g_mask[wi] = fb;
    if (found)  g_v[gid] = make_float2(vx, vy);

    int x = gid & (Wc - 1);
    float fx = (float)x, fy = (float)y;
    float mf = found ? 1.f : 0.f;
    out[2*NPIX + gid] = fx * mf;
    out[3*NPIX + gid] = fy * mf;
    out[4*NPIX + gid] = (fx + vx) * mf;
    out[5*NPIX + gid] = (fy + vy) * mf;
}

// ---------------------------------------------------------------------------
// Kernel 2: sparse splat-as-gather, 32x32 tile, row-bucketed CSR points,
// 4 CONTIGUOUS rows per thread -> each thread only scans 44 of 72 halo rows.
// ---------------------------------------------------------------------------
__global__ void __launch_bounds__(256) splat_kernel(float* __restrict__ out)
{
    __shared__ float  s_K[41*41];
    __shared__ float4 s_pts[CAP];
    __shared__ int    s_rowcnt[HROWS];
    __shared__ int    s_rowofs[HROWS + 1];

    int tid  = threadIdx.x;
    int lane = tid & 31;
    int wrp  = tid >> 5;

    for (int i = tid; i < 41*41; i += 256) s_K[i] = g_K[i];
    if (tid < HROWS) s_rowcnt[tid] = 0;

    int x0 = blockIdx.x * TLX;
    int y0 = blockIdx.y * TLY;
    int b  = blockIdx.z;
    __syncthreads();

    // Phase A: load halo mask words (72 rows x 3 words), count per row.
    unsigned word = 0; int hr = 0, wj = 0, myofs = 0;
    if (tid < HROWS * 3) {
        hr = tid / 3;
        int wi2 = tid % 3 - 1;
        int ry = y0 - 20 + hr;
        wj = (x0 >> 5) + wi2;
        if ((unsigned)ry < (unsigned)Hc && (unsigned)wj < (unsigned)WW) {
            word = g_mask[(b*Hc + ry)*WW + wj];
            if (wi2 == -1) word &= 0xFFFFF000u;   // keep x >= x0-20
            if (wi2 ==  1) word &= 0x000FFFFFu;   // keep x <= x0+51
        }
        if (word) myofs = atomicAdd(&s_rowcnt[hr], __popc(word));
    }
    __syncthreads();

    // Phase B: exclusive prefix sum over 72 row counts (warp 0).
    if (wrp == 0) {
        int carry = 0;
        #pragma unroll
        for (int c = 0; c < 3; c++) {
            int idx  = c*32 + lane;
            int vcnt = (idx < HROWS) ? s_rowcnt[idx] : 0;
            int inc  = vcnt;
            #pragma unroll
            for (int d = 1; d < 32; d <<= 1) {
                int t = __shfl_up_sync(0xFFFFFFFFu, inc, d);
                if (lane >= d) inc += t;
            }
            if (idx <= HROWS) s_rowofs[idx] = inc - vcnt + carry;
            carry += __shfl_sync(0xFFFFFFFFu, inc, 31);
        }
        if (lane == 0) s_rowofs[HROWS] = carry;
    }
    __syncthreads();

    // Phase C: write points bucketed by halo row.
    if (word) {
        int slot = s_rowofs[hr] + myofs;
        int ry   = y0 - 20 + hr;
        unsigned w2 = word;
        while (w2) {
            int jb = __ffs(w2) - 1; w2 &= w2 - 1;
            int px = (wj << 5) + jb;
            float2 v = g_v[(b*Hc + ry)*Wc + px];
            if (slot < CAP)
                s_pts[slot] = make_float4(__int_as_float(px - x0 + 20),
                                          __int_as_float(hr),
                                          v.x, v.y);
            slot++;
        }
    }
    __syncthreads();

    // Main loop: thread (g, tx) owns rows y0+4g .. y0+4g+3 at column x0+tx.
    int tx = lane;
    int g4 = wrp * 4;                          // 4*g
    int beg = min(s_rowofs[g4], CAP);
    int end = min(s_rowofs[min(g4 + 44, HROWS)], CAP);

    float den[4] = {0,0,0,0}, sx[4] = {0,0,0,0}, sy[4] = {0,0,0,0};

    for (int i = beg; i < end; i++) {
        float4 p = s_pts[i];
        int u = __float_as_int(p.x) - tx;            // dx+20
        if ((unsigned)u <= 40u) {
            int v0 = __float_as_int(p.y) - g4;       // dy+20 for row y0+4g
            #pragma unroll
            for (int rr = 0; rr < 4; rr++) {
                int v = v0 - rr;
                if ((unsigned)v <= 40u) {
                    float w = s_K[v*41 + u];
                    den[rr] += w;
                    sx[rr] = fmaf(w, p.z, sx[rr]);
                    sy[rr] = fmaf(w, p.w, sy[rr]);
                }
            }
        }
    }

    int x = x0 + tx;
    float fx = (float)x;
    #pragma unroll
    for (int rr = 0; rr < 4; rr++) {
        int y   = y0 + g4 + rr;
        int idx = (b*Hc + y)*Wc + x;
        float rcp = 1.f / (den[rr] + 1.6f);
        out[idx]        = fx + sx[rr] * rcp;         // morphedx
        out[NPIX + idx] = (float)y + sy[rr] * rcp;   // morphedy
    }
}

extern "C" void kernel_launch(void* const* d_in, const int* in_sizes, int n_in,
                              void* d_out, int out_size)
{
    const float* src = (const float*)d_in[0];  // binMapsrc
    const float* dst = (const float*)d_in[1];  // binMapdst
    const float* xx  = (const float*)d_in[2];
    const float* yy  = (const float*)d_in[3];
    float* out = (float*)d_out;

    bitmask_kernel<<<NPIX/256, 256>>>(src, dst, xx, yy);
    match_kernel<<<NPIX/256, 256>>>(out);

    dim3 grid(Wc/TLX, Hc/TLY, Bc);   // 32 x 10 x 8 = 2560 blocks
    splat_kernel<<<grid, 256>>>(out);

    (void)in_sizes; (void)n_in; (void)out_size;
}

// round 6
// speedup vs baseline: 1.8847x; 1.1199x over previous
#include <cuda_runtime.h>

#define Bc 8
#define Hc 320
#define Wc 1024
#define WW 32                    // 32-bit words per row
#define NPIX (Bc*Hc*Wc)          // 2621440
#define NWORD (NPIX/32)
#define TLX 32
#define TLY 32
#define CAP 1024
#define HROWS 72                 // halo rows per tile: [y0-20, y0+51]
#define KPROWS 47                // padded K table rows: v+3 in [0,46]

// Static device scratch (no allocations)
__device__ unsigned g_srcm[NWORD];
__device__ unsigned g_dstm[NWORD];
__device__ unsigned g_mask[NWORD];     // found bitmask
__device__ float2   g_v[NPIX];         // (vx,vy), sparse at found px
__device__ float    g_Kp[KPROWS*41];   // zero-padded splat weight table
__device__ int      g_rank[7*15];      // argsort-order rank of each (dy,dx)

// ---------------------------------------------------------------------------
// Kernel 0: src/dst bitmasks via float4 loads + fused LUT build.
// Each thread handles 4 consecutive pixels; 8 threads assemble one 32-bit word.
// ---------------------------------------------------------------------------
__global__ void __launch_bounds__(256) bitmask_kernel(
    const float4* __restrict__ src4, const float4* __restrict__ dst4,
    const float* __restrict__ xx,    const float* __restrict__ yy)
{
    int gid  = blockIdx.x * 256 + threadIdx.x;    // covers NPIX/4 threads
    int lane = threadIdx.x & 31;
    int sub  = lane & 7;

    float4 s = src4[gid];
    float4 d = dst4[gid];
    unsigned ns = (s.x > 0.5f) | ((s.y > 0.5f) << 1) |
                  ((s.z > 0.5f) << 2) | ((s.w > 0.5f) << 3);
    unsigned nd = (d.x > 0.5f) | ((d.y > 0.5f) << 1) |
                  ((d.z > 0.5f) << 2) | ((d.w > 0.5f) << 3);
    unsigned vs = ns << (sub * 4);
    unsigned vd = nd << (sub * 4);
    #pragma unroll
    for (int t = 1; t < 8; t <<= 1) {
        vs |= __shfl_xor_sync(0xFFFFFFFFu, vs, t);
        vd |= __shfl_xor_sync(0xFFFFFFFFu, vd, t);
    }
    if (sub == 0) {
        g_srcm[gid >> 3] = vs;
        g_dstm[gid >> 3] = vd;
    }

    if (blockIdx.x < 8) {                          // fused one-shot LUT build
        int i = blockIdx.x * 256 + threadIdx.x;
        if (i < KPROWS*41) {
            int t  = i / 41;            // v+3
            int dx = i % 41 - 20;
            int dy = t - 23;            // v = dy+20 -> t = dy+23
            float w = 0.f;
            if (t >= 3 && t <= 43)
                w = 0.7f * expf(-sqrtf((float)(dx*dx + dy*dy)) * (1.9f/24.f));
            g_Kp[i] = w;
        }
        if (i < 105) {
            int dx = (int)xx[i], dy = (int)yy[i];
            g_rank[(dy + 3)*15 + (dx + 7)] = i;    // exact argsort order
        }
    }
}

// ---------------------------------------------------------------------------
// 15/5-bit neighborhood window extraction from 3 mask words.
// ---------------------------------------------------------------------------
__device__ __forceinline__ unsigned win_extract(
    unsigned l, unsigned m, unsigned r, int j, int radius)
{
    if (j < 16) {
        unsigned long long lm = ((unsigned long long)m << 32) | l;
        return (unsigned)(lm >> (32 + j - radius));
    } else {
        unsigned long long mr = ((unsigned long long)r << 32) | m;
        return (unsigned)(mr >> (j - radius));
    }
}

// ---------------------------------------------------------------------------
// Kernel 1: sparsity filter + nearest-correspondence. Store-light:
// writes only g_mask (1 word/warp) + sparse g_v. ~52% of warps early-out.
// ---------------------------------------------------------------------------
__global__ void __launch_bounds__(256) match_kernel()
{
    __shared__ int s_rank[7*15];
    if (threadIdx.x < 105) s_rank[threadIdx.x] = g_rank[threadIdx.x];
    __syncthreads();

    int gid = blockIdx.x * 256 + threadIdx.x;
    int j   = gid & 31;
    int wi  = gid >> 5;

    unsigned own = g_srcm[wi];               // uniform broadcast load
    if (own == 0) {                          // no active px in this word
        if (j == 0) g_mask[wi] = 0;
        return;
    }

    int wx  = wi & (WW - 1);
    int yb  = wi >> 5;                       // b*H + y
    int y   = yb % Hc;
    int b   = yb / Hc;

    unsigned sw[3][3];
    #pragma unroll
    for (int r = 0; r < 3; r++) {
        int ry = y - 2 + r;
        #pragma unroll
        for (int c = 0; c < 3; c++) {
            int rc = wx - 1 + c;
            unsigned v = 0;
            if ((unsigned)ry < (unsigned)Hc && (unsigned)rc < (unsigned)WW)
                v = g_srcm[(b*Hc + ry)*WW + rc];
            sw[r][c] = v;
        }
    }
    bool active = (own >> j) & 1u;
    unsigned h0 = win_extract(sw[0][0], sw[0][1], sw[0][2], j, 2) & 31u;
    unsigned h1 = win_extract(sw[1][0], sw[1][1], sw[1][2], j, 2) & 31u;
    unsigned h2 = win_extract(sw[2][0], sw[2][1], sw[2][2], j, 2) & 3u;
    bool kept = active && !(h0 | h1 | h2);

    bool found = false;
    float vx = 0.f, vy = 0.f;
    if (__ballot_sync(0xFFFFFFFFu, kept)) {
        int bestkey = 1 << 30, bdx = 0, bdy = 0;
        #pragma unroll
        for (int r = 0; r < 7; r++) {
            int dy = r - 3;
            int ry = y + dy;
            unsigned l = 0, m = 0, rr = 0;
            if ((unsigned)ry < (unsigned)Hc) {
                int base = (b*Hc + ry)*WW;
                if (wx > 0)      l  = g_dstm[base + wx - 1];
                m = g_dstm[base + wx];
                if (wx < WW - 1) rr = g_dstm[base + wx + 1];
            }
            if (kept) {
                unsigned win = win_extract(l, m, rr, j, 7) & 0x7FFFu;
                while (win) {
                    int k = __ffs(win) - 1; win &= win - 1;
                    int key = s_rank[r*15 + k];
                    if (key < bestkey) { bestkey = key; bdx = k - 7; bdy = dy; }
                }
            }
        }
        if (kept && bestkey < (1 << 30)) {
            found = true; vx = (float)bdx; vy = (float)bdy;
        }
    }

    unsigned fb = __ballot_sync(0xFFFFFFFFu, found);
    if (j == 0) g_mask[wi] = fb;
    if (found)  g_v[gid] = make_float2(vx, vy);
}

// ---------------------------------------------------------------------------
// Kernel 2: sparse splat-as-gather, 32x32 tile, row-bucketed CSR points,
// padded K table (no per-row range checks). Also writes channels 2..5.
// ---------------------------------------------------------------------------
__global__ void __launch_bounds__(256) splat_kernel(float* __restrict__ out)
{
    __shared__ float    s_K[KPROWS*41];
    __shared__ float4   s_pts[CAP];
    __shared__ int      s_rowcnt[HROWS];
    __shared__ int      s_rowofs[HROWS + 1];
    __shared__ unsigned s_tw[TLY];           // tile-row found words

    int tid  = threadIdx.x;
    int lane = tid & 31;
    int wrp  = tid >> 5;

    for (int i = tid; i < KPROWS*41; i += 256) s_K[i] = g_Kp[i];
    if (tid < HROWS) s_rowcnt[tid] = 0;

    int x0 = blockIdx.x * TLX;
    int y0 = blockIdx.y * TLY;
    int b  = blockIdx.z;
    __syncthreads();

    // Phase A: load halo mask words (72 rows x 3 words), count per row.
    unsigned word = 0; int hr = 0, wj = 0, myofs = 0;
    if (tid < HROWS * 3) {
        hr = tid / 3;
        int wi2 = tid % 3 - 1;
        int ry = y0 - 20 + hr;
        wj = (x0 >> 5) + wi2;
        if ((unsigned)ry < (unsigned)Hc && (unsigned)wj < (unsigned)WW) {
            word = g_mask[(b*Hc + ry)*WW + wj];
            if (wi2 == 0 && hr >= 20 && hr < 20 + TLY) s_tw[hr - 20] = word;
            if (wi2 == -1) word &= 0xFFFFF000u;   // keep x >= x0-20
            if (wi2 ==  1) word &= 0x000FFFFFu;   // keep x <= x0+51
        }
        if (word) myofs = atomicAdd(&s_rowcnt[hr], __popc(word));
    }
    __syncthreads();

    // Phase B: exclusive prefix sum over 72 row counts (warp 0).
    if (wrp == 0) {
        int carry = 0;
        #pragma unroll
        for (int c = 0; c < 3; c++) {
            int idx  = c*32 + lane;
            int vcnt = (idx < HROWS) ? s_rowcnt[idx] : 0;
            int inc  = vcnt;
            #pragma unroll
            for (int d = 1; d < 32; d <<= 1) {
                int t = __shfl_up_sync(0xFFFFFFFFu, inc, d);
                if (lane >= d) inc += t;
            }
            if (idx <= HROWS) s_rowofs[idx] = inc - vcnt + carry;
            carry += __shfl_sync(0xFFFFFFFFu, inc, 31);
        }
        if (lane == 0) s_rowofs[HROWS] = carry;
    }
    __syncthreads();

    // Phase C: write points bucketed by halo row.
    if (word) {
        int slot = s_rowofs[hr] + myofs;
        int ry   = y0 - 20 + hr;
        unsigned w2 = word;
        while (w2) {
            int jb = __ffs(w2) - 1; w2 &= w2 - 1;
            int px = (wj << 5) + jb;
            float2 v = g_v[(b*Hc + ry)*Wc + px];
            if (slot < CAP)
                s_pts[slot] = make_float4(__int_as_float(px - x0 + 20),
                                          __int_as_float(hr),
                                          v.x, v.y);
            slot++;
        }
    }
    __syncthreads();

    // Main loop: thread (g, tx) owns rows y0+4g .. y0+4g+3 at column x0+tx.
    // CSR guarantees v0 = p.y - 4g in [0,43]; padded table rows absorb rr.
    int tx = lane;
    int g4 = wrp * 4;
    int beg = min(s_rowofs[g4], CAP);
    int end = min(s_rowofs[min(g4 + 44, HROWS)], CAP);

    float den[4] = {0,0,0,0}, sx[4] = {0,0,0,0}, sy[4] = {0,0,0,0};

    for (int i = beg; i < end; i++) {
        float4 p = s_pts[i];
        int u = __float_as_int(p.x) - tx;            // dx+20
        if ((unsigned)u <= 40u) {
            int base = (__float_as_int(p.y) - g4 + 3) * 41 + u;
            #pragma unroll
            for (int rr = 0; rr < 4; rr++) {
                float w = s_K[base - rr*41];
                den[rr] += w;
                sx[rr] = fmaf(w, p.z, sx[rr]);
                sy[rr] = fmaf(w, p.w, sy[rr]);
            }
        }
    }

    int x = x0 + tx;
    float fx = (float)x;
    #pragma unroll
    for (int rr = 0; rr < 4; rr++) {
        int tr  = g4 + rr;
        int y   = y0 + tr;
        int idx = (b*Hc + y)*Wc + x;
        float rcp = 1.f / (den[rr] + 1.6f);
        out[idx]        = fx + sx[rr] * rcp;         // morphedx
        out[NPIX + idx] = (float)y + sy[rr] * rcp;   // morphedy

        bool fnd = (s_tw[tr] >> tx) & 1u;
        float vx = 0.f, vy = 0.f;
        if (fnd) { float2 gv = g_v[idx]; vx = gv.x; vy = gv.y; }
        float mf = fnd ? 1.f : 0.f;
        float fy = (float)y;
        out[2*NPIX + idx] = fx * mf;                 // orgpts_x
        out[3*NPIX + idx] = fy * mf;                 // orgpts_y
        out[4*NPIX + idx] = (fx + vx) * mf;          // correspts_x
        out[5*NPIX + idx] = (fy + vy) * mf;          // correspts_y
    }
}

extern "C" void kernel_launch(void* const* d_in, const int* in_sizes, int n_in,
                              void* d_out, int out_size)
{
    const float4* src4 = (const float4*)d_in[0];  // binMapsrc
    const float4* dst4 = (const float4*)d_in[1];  // binMapdst
    const float*  xx   = (const float*)d_in[2];
    const float*  yy   = (const float*)d_in[3];
    float* out = (float*)d_out;

    bitmask_kernel<<<NPIX/1024, 256>>>(src4, dst4, xx, yy);
    match_kernel<<<NPIX/256, 256>>>();

    dim3 grid(Wc/TLX, Hc/TLY, Bc);   // 32 x 10 x 8 = 2560 blocks
    splat_kernel<<<grid, 256>>>(out);

    (void)in_sizes; (void)n_in; (void)out_size;
}

// round 8
// speedup vs baseline: 1.9361x; 1.0273x over previous
#include <cuda_runtime.h>

#define Bc 8
#define Hc 320
#define Wc 1024
#define WW 32                    // 32-bit words per row
#define NPIX (Bc*Hc*Wc)          // 2621440
#define NWORD (NPIX/32)
#define TLX 32
#define TLY 32
#define CAP 1024
#define HROWS 72                 // halo rows per tile: [y0-20, y0+51]
#define KPROWS 47                // padded K rows: t = v+3 in [0,46]

// Static device scratch (no allocations)
__device__ unsigned g_srcm[NWORD];
__device__ unsigned g_dstm[NWORD];
__device__ unsigned g_mask[NWORD];     // found bitmask
__device__ float2   g_v[NPIX];         // (vx,vy), sparse at found px
__device__ float2   g_K2[KPROWS*41];   // row-paired K table: (K[t], K[t-1])
__device__ int      g_rank[7*15];      // argsort-order rank of each (dy,dx)

// ---- f32x2 helpers -------------------------------------------------------
__device__ __forceinline__ unsigned long long f2u(float a, float b) {
    unsigned long long r;
    asm("mov.b64 %0, {%1,%2};" : "=l"(r) : "f"(a), "f"(b));
    return r;
}
__device__ __forceinline__ float2 u2f(unsigned long long v) {
    float2 r;
    asm("mov.b64 {%0,%1}, %2;" : "=f"(r.x), "=f"(r.y) : "l"(v));
    return r;
}
__device__ __forceinline__ void fma2(unsigned long long& acc,
                                     unsigned long long a,
                                     unsigned long long b) {
    asm("fma.rn.f32x2 %0, %1, %2, %0;" : "+l"(acc) : "l"(a), "l"(b));
}

__device__ __forceinline__ float kw(int t, int dx) {   // padded K row value
    if (t < 3 || t > 43) return 0.f;
    int dy = t - 23;
    return 0.7f * expf(-sqrtf((float)(dx*dx + dy*dy)) * (1.9f/24.f));
}

// ---------------------------------------------------------------------------
// Kernel 0: bitmasks, 8 px/thread (4x LDG.128, MLP=4) + fused LUT build.
// ---------------------------------------------------------------------------
__global__ void __launch_bounds__(256) bitmask_kernel(
    const float4* __restrict__ src4, const float4* __restrict__ dst4,
    const float* __restrict__ xx,    const float* __restrict__ yy)
{
    int t    = blockIdx.x * 256 + threadIdx.x;    // NPIX/8 threads
    int sub  = threadIdx.x & 3;                   // 4 threads per mask word

    float4 s0 = src4[2*t], s1 = src4[2*t + 1];
    float4 d0 = dst4[2*t], d1 = dst4[2*t + 1];
    unsigned ns = (s0.x > 0.5f)        | ((s0.y > 0.5f) << 1) |
                  ((s0.z > 0.5f) << 2) | ((s0.w > 0.5f) << 3) |
                  ((s1.x > 0.5f) << 4) | ((s1.y > 0.5f) << 5) |
                  ((s1.z > 0.5f) << 6) | ((s1.w > 0.5f) << 7);
    unsigned nd = (d0.x > 0.5f)        | ((d0.y > 0.5f) << 1) |
                  ((d0.z > 0.5f) << 2) | ((d0.w > 0.5f) << 3) |
                  ((d1.x > 0.5f) << 4) | ((d1.y > 0.5f) << 5) |
                  ((d1.z > 0.5f) << 6) | ((d1.w > 0.5f) << 7);
    unsigned vs = ns << (sub * 8);
    unsigned vd = nd << (sub * 8);
    #pragma unroll
    for (int m = 1; m < 4; m <<= 1) {
        vs |= __shfl_xor_sync(0xFFFFFFFFu, vs, m);
        vd |= __shfl_xor_sync(0xFFFFFFFFu, vd, m);
    }
    if (sub == 0) { g_srcm[t >> 2] = vs; g_dstm[t >> 2] = vd; }

    if (blockIdx.x < 8) {                          // one-shot LUT build
        int i = blockIdx.x * 256 + threadIdx.x;
        if (i < KPROWS*41) {
            int tt = i / 41, dx = i % 41 - 20;
            g_K2[i] = make_float2(kw(tt, dx), kw(tt - 1, dx));
        }
        if (i < 105) {
            int dx = (int)xx[i], dy = (int)yy[i];
            g_rank[(dy + 3)*15 + (dx + 7)] = i;    // exact argsort order
        }
    }
}

// ---------------------------------------------------------------------------
// 15/5-bit neighborhood window extraction from 3 mask words.
// ---------------------------------------------------------------------------
__device__ __forceinline__ unsigned win_extract(
    unsigned l, unsigned m, unsigned r, int j, int radius)
{
    if (j < 16) {
        unsigned long long lm = ((unsigned long long)m << 32) | l;
        return (unsigned)(lm >> (32 + j - radius));
    } else {
        unsigned long long mr = ((unsigned long long)r << 32) | m;
        return (unsigned)(mr >> (j - radius));
    }
}

// ---------------------------------------------------------------------------
// Kernel 1: sparsity filter + nearest-correspondence (bitmask windows).
// ---------------------------------------------------------------------------
__global__ void __launch_bounds__(256) match_kernel()
{
    __shared__ int s_rank[7*15];
    if (threadIdx.x < 105) s_rank[threadIdx.x] = g_rank[threadIdx.x];
    __syncthreads();

    int gid = blockIdx.x * 256 + threadIdx.x;
    int j   = gid & 31;
    int wi  = gid >> 5;

    unsigned own = g_srcm[wi];
    if (own == 0) {                          // early-out (~52% of warps)
        if (j == 0) g_mask[wi] = 0;
        return;
    }

    int wx  = wi & (WW - 1);
    int yb  = wi >> 5;
    int y   = yb % Hc;
    int b   = yb / Hc;

    unsigned sw[3][3];
    #pragma unroll
    for (int r = 0; r < 3; r++) {
        int ry = y - 2 + r;
        #pragma unroll
        for (int c = 0; c < 3; c++) {
            int rc = wx - 1 + c;
            unsigned v = 0;
            if ((unsigned)ry < (unsigned)Hc && (unsigned)rc < (unsigned)WW)
                v = g_srcm[(b*Hc + ry)*WW + rc];
            sw[r][c] = v;
        }
    }
    bool active = (own >> j) & 1u;
    unsigned h0 = win_extract(sw[0][0], sw[0][1], sw[0][2], j, 2) & 31u;
    unsigned h1 = win_extract(sw[1][0], sw[1][1], sw[1][2], j, 2) & 31u;
    unsigned h2 = win_extract(sw[2][0], sw[2][1], sw[2][2], j, 2) & 3u;
    bool kept = active && !(h0 | h1 | h2);

    bool found = false;
    float vx = 0.f, vy = 0.f;
    if (__ballot_sync(0xFFFFFFFFu, kept)) {
        int bestkey = 1 << 30, bdx = 0, bdy = 0;
        #pragma unroll
        for (int r = 0; r < 7; r++) {
            int dy = r - 3;
            int ry = y + dy;
            unsigned l = 0, m = 0, rr = 0;
            if ((unsigned)ry < (unsigned)Hc) {
                int base = (b*Hc + ry)*WW;
                if (wx > 0)      l  = g_dstm[base + wx - 1];
                m = g_dstm[base + wx];
                if (wx < WW - 1) rr = g_dstm[base + wx + 1];
            }
            if (kept) {
                unsigned win = win_extract(l, m, rr, j, 7) & 0x7FFFu;
                while (win) {
                    int k = __ffs(win) - 1; win &= win - 1;
                    int key = s_rank[r*15 + k];
                    if (key < bestkey) { bestkey = key; bdx = k - 7; bdy = dy; }
                }
            }
        }
        if (kept && bestkey < (1 << 30)) {
            found = true; vx = (float)bdx; vy = (float)bdy;
        }
    }

    unsigned fb = __ballot_sync(0xFFFFFFFFu, found);
    if (j == 0) g_mask[wi] = fb;
    if (found)  g_v[gid] = make_float2(vx, vy);
}

// ---------------------------------------------------------------------------
// Kernel 2: sparse splat-as-gather, row-bucketed CSR, f32x2 packed taps.
// ---------------------------------------------------------------------------
__global__ void __launch_bounds__(256) splat_kernel(float* __restrict__ out)
{
    __shared__ float2   s_K2[KPROWS*41];
    __shared__ float4   s_pts[CAP];
    __shared__ int      s_rowcnt[HROWS];
    __shared__ int      s_rowofs[HROWS + 1];
    __shared__ unsigned s_tw[TLY];           // tile-row found words

    int tid  = threadIdx.x;
    int lane = tid & 31;
    int wrp  = tid >> 5;

    for (int i = tid; i < KPROWS*41; i += 256) s_K2[i] = g_K2[i];
    if (tid < HROWS) s_rowcnt[tid] = 0;

    int x0 = blockIdx.x * TLX;
    int y0 = blockIdx.y * TLY;
    int b  = blockIdx.z;
    __syncthreads();

    // Phase A: load halo mask words (72 rows x 3 words), count per row.
    unsigned word = 0; int hr = 0, wj = 0, myofs = 0;
    if (tid < HROWS * 3) {
        hr = tid / 3;
        int wi2 = tid % 3 - 1;
        int ry = y0 - 20 + hr;
        wj = (x0 >> 5) + wi2;
        if ((unsigned)ry < (unsigned)Hc && (unsigned)wj < (unsigned)WW) {
            word = g_mask[(b*Hc + ry)*WW + wj];
            if (wi2 == 0 && hr >= 20 && hr < 20 + TLY) s_tw[hr - 20] = word;
            if (wi2 == -1) word &= 0xFFFFF000u;   // keep x >= x0-20
            if (wi2 ==  1) word &= 0x000FFFFFu;   // keep x <= x0+51
        }
        if (word) myofs = atomicAdd(&s_rowcnt[hr], __popc(word));
    }
    __syncthreads();

    // Phase B: exclusive prefix sum over 72 row counts (warp 0).
    if (wrp == 0) {
        int carry = 0;
        #pragma unroll
        for (int c = 0; c < 3; c++) {
            int idx  = c*32 + lane;
            int vcnt = (idx < HROWS) ? s_rowcnt[idx] : 0;
            int inc  = vcnt;
            #pragma unroll
            for (int d = 1; d < 32; d <<= 1) {
                int t2 = __shfl_up_sync(0xFFFFFFFFu, inc, d);
                if (lane >= d) inc += t2;
            }
            if (idx <= HROWS) s_rowofs[idx] = inc - vcnt + carry;
            carry += __shfl_sync(0xFFFFFFFFu, inc, 31);
        }
        if (lane == 0) s_rowofs[HROWS] = carry;
    }
    __syncthreads();

    // Phase C: write points bucketed by halo row.
    if (word) {
        int slot = s_rowofs[hr] + myofs;
        int ry   = y0 - 20 + hr;
        unsigned w2 = word;
        while (w2) {
            int jb = __ffs(w2) - 1; w2 &= w2 - 1;
            int px = (wj << 5) + jb;
            float2 v = g_v[(b*Hc + ry)*Wc + px];
            if (slot < CAP)
                s_pts[slot] = make_float4(__int_as_float(px - x0 + 20),
                                          __int_as_float(hr),
                                          v.x, v.y);
            slot++;
        }
    }
    __syncthreads();

    // Main loop: thread (g, tx) owns rows y0+4g..y0+4g+3 at column x0+tx.
    // v0 = p.y - 4g in [0,43]; s_K2[t] = (K[t], K[t-1]) gives row pairs.
    int tx = lane;
    int g4 = wrp * 4;
    int beg = min(s_rowofs[g4], CAP);
    int end = min(s_rowofs[min(g4 + 44, HROWS)], CAP);

    unsigned long long dd01 = 0, dd23 = 0, xx01 = 0, xx23 = 0, yy01 = 0, yy23 = 0;
    const unsigned long long ones = f2u(1.f, 1.f);

    for (int i = beg; i < end; i++) {
        float4 p = s_pts[i];
        int u = __float_as_int(p.x) - tx;            // dx+20
        if ((unsigned)u <= 40u) {
            int t0 = (__float_as_int(p.y) - g4 + 3) * 41 + u;
            unsigned long long w01 =
                *reinterpret_cast<const unsigned long long*>(&s_K2[t0]);
            unsigned long long w23 =
                *reinterpret_cast<const unsigned long long*>(&s_K2[t0 - 82]);
            unsigned long long pz2 = f2u(p.z, p.z);
            unsigned long long pw2 = f2u(p.w, p.w);
            fma2(dd01, w01, ones);
            fma2(xx01, w01, pz2);
            fma2(yy01, w01, pw2);
            fma2(dd23, w23, ones);
            fma2(xx23, w23, pz2);
            fma2(yy23, w23, pw2);
        }
    }

    float2 d01 = u2f(dd01), d23 = u2f(dd23);
    float2 x01 = u2f(xx01), x23 = u2f(xx23);
    float2 y01 = u2f(yy01), y23 = u2f(yy23);
    float den[4] = {d01.x, d01.y, d23.x, d23.y};
    float sx[4]  = {x01.x, x01.y, x23.x, x23.y};
    float sy[4]  = {y01.x, y01.y, y23.x, y23.y};

    int x = x0 + tx;
    float fx = (float)x;
    #pragma unroll
    for (int rr = 0; rr < 4; rr++) {
        int tr  = g4 + rr;
        int y   = y0 + tr;
        int idx = (b*Hc + y)*Wc + x;
        float rcp = 1.f / (den[rr] + 1.6f);
        out[idx]        = fx + sx[rr] * rcp;         // morphedx
        out[NPIX + idx] = (float)y + sy[rr] * rcp;   // morphedy

        bool fnd = (s_tw[tr] >> tx) & 1u;
        float vx = 0.f, vy = 0.f;
        if (fnd) { float2 gv = g_v[idx]; vx = gv.x; vy = gv.y; }
        float mf = fnd ? 1.f : 0.f;
        float fy = (float)y;
        out[2*NPIX + idx] = fx * mf;                 // orgpts_x
        out[3*NPIX + idx] = fy * mf;                 // orgpts_y
        out[4*NPIX + idx] = (fx + vx) * mf;          // correspts_x
        out[5*NPIX + idx] = (fy + vy) * mf;          // correspts_y
    }
}

extern "C" void kernel_launch(void* const* d_in, const int* in_sizes, int n_in,
                              void* d_out, int out_size)
{
    const float4* src4 = (const float4*)d_in[0];  // binMapsrc
    const float4* dst4 = (const float4*)d_in[1];  // binMapdst
    const float*  xx   = (const float*)d_in[2];
    const float*  yy   = (const float*)d_in[3];
    float* out = (float*)d_out;

    bitmask_kernel<<<NPIX/2048, 256>>>(src4, dst4, xx, yy);
    match_kernel<<<NPIX/256, 256>>>();

    dim3 grid(Wc/TLX, Hc/TLY, Bc);   // 32 x 10 x 8 = 2560 blocks
    splat_kernel<<<grid, 256>>>(out);

    (void)in_sizes; (void)n_in; (void)out_size;
}